// round 16
// baseline (speedup 1.0000x reference)
#include <cuda_runtime.h>
#include <cuda_fp16.h>
#include <mma.h>
#include <math.h>
#include <cstdint>

using namespace nvcuda;

#define B_   2
#define LQ_  1024
#define LK_  1024
#define D_   1024
#define H_   16
#define DH_  64
#define BH_  (B_ * H_)
#define NEG_BIG (-3.402823466e38f)
#define L2E_ 1.44269504f

// ---------------- scratch ----------------------------------------------------
__device__ __half g_xh3[3 * 2048 * 1024];         // staged inputs q/k/v (half); slot0 reused for att
__device__ __half g_wh4[4 * 1024 * 1024];         // staged weights Wq/Wk/Wv/Wo (half)
__device__ __half g_qh[2048 * 1024];              // projected Q (half)
__device__ __half g_kh[2048 * 1024];              // projected K, COMPACTED rows (half)
__device__ __half g_vh[2048 * 1024];              // projected V, COMPACTED rows (half)
__device__ float  g_lbc[B_ * LQ_ * LK_];          // compacted bias (+fb, NEG_BIG tail)
__device__ int    g_mask_kind;
__device__ int    g_idx[B_][LK_];                 // compacted key indices (padded w/ 0)
__device__ int    g_destg[B_ * LK_];              // src row -> absolute compacted row, -1 drop
__device__ int    g_nsel[B_];
__device__ float  g_fb[B_];

// ---------------- helpers -----------------------------------------------------
__device__ __forceinline__ void cp16(unsigned int dst, const void* src) {
    asm volatile("cp.async.cg.shared.global [%0], [%1], 16;\n" :: "r"(dst), "l"(src));
}
__device__ __forceinline__ void cp_commit() {
    asm volatile("cp.async.commit_group;\n" ::: "memory");
}
__device__ __forceinline__ unsigned int smem_u32(const void* ptr) {
    unsigned int a;
    asm("{ .reg .u64 t; cvta.to.shared.u64 t, %1; cvt.u32.u64 %0, t; }" : "=r"(a) : "l"(ptr));
    return a;
}
__device__ __forceinline__ void ldsm4(unsigned& r0, unsigned& r1, unsigned& r2, unsigned& r3,
                                      unsigned addr) {
    asm volatile("ldmatrix.sync.aligned.m8n8.x4.shared.b16 {%0,%1,%2,%3}, [%4];"
                 : "=r"(r0), "=r"(r1), "=r"(r2), "=r"(r3) : "r"(addr));
}
__device__ __forceinline__ void ldsm4t(unsigned& r0, unsigned& r1, unsigned& r2, unsigned& r3,
                                       unsigned addr) {
    asm volatile("ldmatrix.sync.aligned.m8n8.x4.trans.shared.b16 {%0,%1,%2,%3}, [%4];"
                 : "=r"(r0), "=r"(r1), "=r"(r2), "=r"(r3) : "r"(addr));
}
__device__ __forceinline__ void ldsm2t(unsigned& r0, unsigned& r1, unsigned addr) {
    asm volatile("ldmatrix.sync.aligned.m8n8.x2.trans.shared.b16 {%0,%1}, [%2];"
                 : "=r"(r0), "=r"(r1) : "r"(addr));
}
__device__ __forceinline__ void mma16816(float* d, const unsigned* a, unsigned b0, unsigned b1) {
    asm volatile(
        "mma.sync.aligned.m16n8k16.row.col.f32.f16.f16.f32 "
        "{%0,%1,%2,%3}, {%4,%5,%6,%7}, {%8,%9}, {%0,%1,%2,%3};"
        : "+f"(d[0]), "+f"(d[1]), "+f"(d[2]), "+f"(d[3])
        : "r"(a[0]), "r"(a[1]), "r"(a[2]), "r"(a[3]), "r"(b0), "r"(b1));
}
__device__ __forceinline__ unsigned pack_ex2(float x, float y, float mn) {
    __half2 t = __floats2half2_rn((x - mn) * L2E_, (y - mn) * L2E_);
    unsigned u = *reinterpret_cast<unsigned*>(&t);
    unsigned r;
    asm("ex2.approx.f16x2 %0, %1;" : "=r"(r) : "r"(u));
    return r;
}

__device__ __forceinline__ bool mask_true(const void* m, int kind, int idx) {
    if (kind == 0) return ((const int*)m)[idx] != 0;
    if (kind == 1) return ((const float*)m)[idx] != 0.0f;
    return ((const unsigned char*)m)[idx] != 0;
}

// ---------------- prep: dtype detect + compaction maps ------------------------
__global__ void prep_kernel(const void* mask) {
    if (threadIdx.x == 0) {
        const unsigned int* m = (const unsigned int*)mask;
        int all01 = 1, allf = 1;
        for (int i = 0; i < 512; i++) {
            unsigned v = m[i];
            if (v > 1u) all01 = 0;
            if (v != 0u && v != 0x3F800000u) allf = 0;
        }
        g_mask_kind = all01 ? 0 : (allf ? 1 : 2);
    }
    __syncthreads();
    const int kind = g_mask_kind;
    const int w = threadIdx.x >> 5;
    const int lane = threadIdx.x & 31;
    if (w >= B_) return;

    // init dest map to -1
    for (int j = lane; j < LK_; j += 32) g_destg[w * LK_ + j] = -1;
    __syncwarp();

    int base = 0;
    for (int c = 0; c < 32; c++) {
        int j = c * 32 + lane;
        bool keep = !mask_true(mask, kind, w * LK_ + j);
        unsigned bal = __ballot_sync(0xffffffffu, keep);
        int pos = base + __popc(bal & ((1u << lane) - 1u));
        if (keep) {
            g_idx[w][pos] = j;
            g_destg[w * LK_ + j] = w * LK_ + pos;
        }
        base += __popc(bal);
    }
    __syncwarp();
    if (base == 0) {
        // all masked: identity -> dense 16-tile loop, NEG_BIG additive
        for (int j = lane; j < LK_; j += 32) {
            g_idx[w][j] = j;
            g_destg[w * LK_ + j] = w * LK_ + j;
        }
        if (lane == 0) { g_nsel[w] = LK_; g_fb[w] = NEG_BIG; }
    } else {
        for (int j = base + lane; j < LK_; j += 32) g_idx[w][j] = 0;
        if (lane == 0) { g_nsel[w] = base; g_fb[w] = 0.0f; }
    }
}

// ---------------- zero tail rows [nsel, padded) of compacted K/V --------------
__global__ void fill_tail_kernel() {
    const int b = blockIdx.x;
    const int which = blockIdx.y;
    const int nsel = g_nsel[b];
    const int padded = (nsel + 63) & ~63;
    const int nrows = padded - nsel;
    if (nrows <= 0) return;
    __half* dst = which ? g_vh : g_kh;
    const int total = nrows * 128;   // uint4 chunks per row = 128
    for (int i = threadIdx.x; i < total; i += blockDim.x) {
        int r = nsel + i / 128, off = (i % 128) * 8;
        uint4 z = {0u, 0u, 0u, 0u};
        *(uint4*)&dst[(size_t)(b * LK_ + r) * 1024 + off] = z;
    }
}

// ---------------- compact bias: g_lbc[b][q][j] = lb[b][q][idx[j]] + fb --------
__global__ __launch_bounds__(256) void compact_bias_kernel(const float* __restrict__ lb) {
    const int q = blockIdx.x;
    const int b = blockIdx.y;
    const int nsel = g_nsel[b];
    const int padded = (nsel + 63) & ~63;
    const float fb = g_fb[b];
    const float* src = lb + (size_t)(b * LQ_ + q) * LK_;
    float* dst = g_lbc + (size_t)(b * LQ_ + q) * LK_;
    for (int j = threadIdx.x; j < padded; j += 256) {
        int c = __ldg(&g_idx[b][j]);
        dst[j] = (j < nsel) ? src[c] + fb : NEG_BIG;
    }
}

// ---------------- fp32 -> fp16 convert (single launch, 7 slices) -------------
__device__ __forceinline__ void cvt8(const float* __restrict__ x, __half* __restrict__ y, int i) {
    float4 a = *(const float4*)&x[i];
    float4 b = *(const float4*)&x[i + 4];
    __half h[8];
    h[0] = __float2half_rn(a.x); h[1] = __float2half_rn(a.y);
    h[2] = __float2half_rn(a.z); h[3] = __float2half_rn(a.w);
    h[4] = __float2half_rn(b.x); h[5] = __float2half_rn(b.y);
    h[6] = __float2half_rn(b.z); h[7] = __float2half_rn(b.w);
    *(uint4*)&y[i] = *(uint4*)h;
}

__global__ __launch_bounds__(256) void cvt_all(
    const float* __restrict__ q, const float* __restrict__ k, const float* __restrict__ v,
    const float* __restrict__ w0, const float* __restrict__ w1,
    const float* __restrict__ w2, const float* __restrict__ w3,
    __half* __restrict__ xh3, __half* __restrict__ wh4)
{
    const int z = blockIdx.z;
    const int i = (blockIdx.x * 256 + threadIdx.x) * 8;
    if (z < 3) {
        const float* x = (z == 0) ? q : (z == 1) ? k : v;
        cvt8(x, xh3 + (size_t)z * 2048 * 1024, i);
    } else {
        if (i >= 1024 * 1024) return;
        const int wz = z - 3;
        const float* x = (wz == 0) ? w0 : (wz == 1) ? w1 : (wz == 2) ? w2 : w3;
        cvt8(x, wh4 + (size_t)wz * 1024 * 1024, i);
    }
}

// ---------------- fp16 GEMM core: C[2048,1024] = A @ W^T + bias --------------
// BM=128 BN=128 BK=64; 3-stage cp.async pipeline; ONE barrier per K-iter.
// Optional row-scatter via dest map (compaction of K/V outputs).
#define GEMM_SMEM 110592

__device__ __forceinline__ void gemm_load_stage(
    unsigned int sb, int stage, int m0, int n0, int kc0, int tid,
    const __half* __restrict__ A, const __half* __restrict__ Wm)
{
    const unsigned int base = (unsigned int)(stage * 18432) * 2;
    #pragma unroll
    for (int u = 0; u < 4; u++) {
        int f = tid + u * 256;
        int r = f >> 3, ch = f & 7;
        unsigned int off = base + (unsigned int)(r * 72 + ch * 8) * 2;
        cp16(sb + off,             A  + (size_t)(m0 + r) * 1024 + kc0 + ch * 8);
        cp16(sb + off + 9216 * 2,  Wm + (size_t)(n0 + r) * 1024 + kc0 + ch * 8);
    }
}

__device__ __forceinline__ void gemm_core(
    char* smc, const __half* __restrict__ A, const __half* __restrict__ Wm,
    const float* __restrict__ bias, void* __restrict__ Cout, int out_is_half,
    const int* __restrict__ dest)
{
    __half* Sh = (__half*)smc;
    float*  Ss = (float*)smc;

    const int tid = threadIdx.x;
    const int w = tid >> 5;
    const int m0 = blockIdx.y * 128, n0 = blockIdx.x * 128;
    const int wm = w >> 2, wn = w & 3;

    const unsigned int sb = smem_u32(Sh);

    wmma::fragment<wmma::accumulator, 16, 16, 16, float> c[4][2];
    #pragma unroll
    for (int i = 0; i < 4; i++)
        #pragma unroll
        for (int j = 0; j < 2; j++)
            wmma::fill_fragment(c[i][j], 0.0f);

    gemm_load_stage(sb, 0, m0, n0, 0,  tid, A, Wm); cp_commit();
    gemm_load_stage(sb, 1, m0, n0, 64, tid, A, Wm); cp_commit();

    for (int t = 0; t < 16; t++) {
        if (t == 15) asm volatile("cp.async.wait_group 0;" ::: "memory");
        else         asm volatile("cp.async.wait_group 1;" ::: "memory");
        __syncthreads();

        if (t + 2 < 16) {
            gemm_load_stage(sb, (t + 2) % 3, m0, n0, (t + 2) * 64, tid, A, Wm);
            cp_commit();
        }

        const __half* Ab = Sh + (t % 3) * 18432;
        const __half* Wb = Ab + 9216;
        #pragma unroll
        for (int kk = 0; kk < 64; kk += 16) {
            wmma::fragment<wmma::matrix_a, 16, 16, 16, __half, wmma::row_major> a[4];
            wmma::fragment<wmma::matrix_b, 16, 16, 16, __half, wmma::col_major> bf[2];
            #pragma unroll
            for (int i = 0; i < 4; i++)
                wmma::load_matrix_sync(a[i], Ab + (wm * 64 + i * 16) * 72 + kk, 72);
            #pragma unroll
            for (int j = 0; j < 2; j++)
                wmma::load_matrix_sync(bf[j], Wb + (wn * 32 + j * 16) * 72 + kk, 72);
            #pragma unroll
            for (int i = 0; i < 4; i++)
                #pragma unroll
                for (int j = 0; j < 2; j++)
                    wmma::mma_sync(c[i][j], a[i], bf[j], c[i][j]);
        }
    }

    __syncthreads();
    #pragma unroll
    for (int i = 0; i < 4; i++)
        #pragma unroll
        for (int j = 0; j < 2; j++)
            wmma::store_matrix_sync(&Ss[(wm * 64 + i * 16) * 132 + wn * 32 + j * 16],
                                    c[i][j], 132, wmma::mem_row_major);
    __syncthreads();

    if (out_is_half) {
        __half* C = (__half*)Cout;
        #pragma unroll
        for (int u = 0; u < 8; u++) {
            int f = tid + u * 256;
            int r = f >> 4, ch = f & 15;
            int dr = dest ? dest[m0 + r] : (m0 + r);
            if (dr < 0) continue;
            const float* src = &Ss[r * 132 + ch * 8];
            const float* bp = &bias[n0 + ch * 8];
            __half hv[8];
            #pragma unroll
            for (int e = 0; e < 8; e++) hv[e] = __float2half_rn(src[e] + bp[e]);
            *(uint4*)&C[(size_t)dr * 1024 + n0 + ch * 8] = *(uint4*)hv;
        }
    } else {
        float* C = (float*)Cout;
        #pragma unroll
        for (int u = 0; u < 8; u++) {
            int f = tid + u * 256;
            int r = f >> 4, ch = f & 15;
            const float* src = &Ss[r * 132 + ch * 8];
            const float* bp = &bias[n0 + ch * 8];
            float ov[8];
            #pragma unroll
            for (int e = 0; e < 8; e++) ov[e] = src[e] + bp[e];
            *(float4*)&C[(size_t)(m0 + r) * 1024 + n0 + ch * 8] = *(float4*)ov;
            *(float4*)&C[(size_t)(m0 + r) * 1024 + n0 + ch * 8 + 4] = *(float4*)&ov[4];
        }
    }
}

__global__ __launch_bounds__(256) void gemm_qkv(
    const __half* __restrict__ Abase, const __half* __restrict__ Wbase,
    const float* __restrict__ b0, const float* __restrict__ b1, const float* __restrict__ b2,
    __half* __restrict__ C0, __half* __restrict__ C1, __half* __restrict__ C2)
{
    extern __shared__ char smc[];
    const int z = blockIdx.z;
    const float* bias = (z == 0) ? b0 : (z == 1) ? b1 : b2;
    __half* C = (z == 0) ? C0 : (z == 1) ? C1 : C2;
    const int* dest = (z == 0) ? (const int*)nullptr : g_destg;
    gemm_core(smc, Abase + (size_t)z * 2048 * 1024,
              Wbase + (size_t)z * 1024 * 1024, bias, C, 1, dest);
}

__global__ __launch_bounds__(256) void gemm_out(
    const __half* __restrict__ A, const __half* __restrict__ Wm,
    const float* __restrict__ bias, float* __restrict__ C)
{
    extern __shared__ char smc[];
    gemm_core(smc, A, Wm, bias, C, 0, nullptr);
}

// ---------------- flash attention (FA2, dense over compacted keys) -----------
// q-tile 128 (8 warps x 16 rows), k-tile 64; K/V/bias are pre-compacted so the
// hot loop is identical to the dense round-14 version, just fewer tiles.
// smem: Qs[128][72]h + Ks[2][64][72]h + Vs[2][64][72]h = 55296 B
#define FLASH_SMEM 55296

__global__ __launch_bounds__(256, 2) void flash_attn(
    __half* __restrict__ outh)
{
    extern __shared__ char smc[];
    __half* Qs = (__half*)smc;                 // [128][72]
    __half* Ks = Qs + 128 * 72;                // [2][64][72]
    __half* Vs = Ks + 2 * 64 * 72;             // [2][64][72]

    const int tid = threadIdx.x;
    const int w = tid >> 5, lane = tid & 31;
    const int q0 = blockIdx.x * 128;
    const int bh = blockIdx.y;
    const int b = bh >> 4, h = bh & 15;
    const int hc = h * DH_;
    const int qw0 = w * 16;
    const int rowid = lane >> 2, cc2 = (lane & 3) * 2;

    const int ntiles = (g_nsel[b] + 63) >> 6;

    const unsigned sQ = smem_u32(Qs);
    const unsigned sK = smem_u32(Ks);
    const unsigned sV = smem_u32(Vs);

    // stage Q (x0.125), 128x64 half
    const __half2 sc2 = __float2half2_rn(0.125f);
    #pragma unroll
    for (int u = 0; u < 4; u++) {
        int f = tid + u * 256;
        int r = f >> 3, ch = f & 7;
        uint4 qv = *(const uint4*)&g_qh[(size_t)(b * LQ_ + q0 + r) * 1024 + hc + ch * 8];
        __half2* qp = (__half2*)&qv;
        #pragma unroll
        for (int e = 0; e < 4; e++) qp[e] = __hmul2(qp[e], sc2);
        *(uint4*)&Qs[r * 72 + ch * 8] = qv;
    }
    // ones column (col 64) + zero pad (65..71) for V, both buffers
    for (int i = tid; i < 128; i += 256) {
        int bu = i >> 6, r = i & 63;
        uint4 z; z.x = 0x00003C00u; z.y = 0u; z.z = 0u; z.w = 0u;
        *(uint4*)&Vs[bu * 64 * 72 + r * 72 + 64] = z;
    }

    #define KV_LOAD(buf, kc0)                                                        \
    {                                                                                \
        _Pragma("unroll")                                                            \
        for (int u = 0; u < 2; u++) {                                                \
            int f = tid + u * 256;                                                   \
            int r = f >> 3, ch = f & 7;                                              \
            unsigned int off = (unsigned)((buf) * 64 * 72 + r * 72 + ch * 8) * 2;    \
            size_t g = (size_t)(b * LK_ + (kc0) + r) * 1024 + hc + ch * 8;           \
            cp16(sK + off, &g_kh[g]);                                                \
            cp16(sV + off, &g_vh[g]);                                                \
        }                                                                            \
    }

    KV_LOAD(0, 0); cp_commit();
    __syncthreads();

    // Q fragments (persistent): qa[ks][0..3]
    unsigned qa[4][4];
    {
        unsigned qaddr = sQ + (unsigned)((qw0 + ((lane >> 3) & 1) * 8 + (lane & 7)) * 144
                                         + (lane >> 4) * 16);
        #pragma unroll
        for (int ks = 0; ks < 4; ks++)
            ldsm4(qa[ks][0], qa[ks][1], qa[ks][2], qa[ks][3], qaddr + ks * 32);
    }

    // ldmatrix lane-offsets
    const unsigned koff = (unsigned)(((lane >> 4) * 8 + (lane & 7)) * 144 + ((lane >> 3) & 1) * 16);
    const unsigned voff = (unsigned)(((( lane >> 3) & 1) * 8 + (lane & 7)) * 144 + (lane >> 4) * 16);
    const unsigned ooff = (unsigned)(((( lane >> 3) & 1) * 8 + (lane & 7)) * 144 + 128);

    float oc[9][4];
    #pragma unroll
    for (int nt = 0; nt < 9; nt++)
        #pragma unroll
        for (int j = 0; j < 4; j++) oc[nt][j] = 0.0f;
    float m0 = NEG_BIG, m1 = NEG_BIG;

    const float* lbr0 = g_lbc + (size_t)(b * LQ_ + q0 + qw0 + rowid) * 1024;
    const float* lbr1 = lbr0 + 8 * 1024;

    for (int t = 0; t < ntiles; t++) {
        const int buf = t & 1;
        asm volatile("cp.async.wait_group 0;" ::: "memory");
        __syncthreads();
        if (t + 1 < ntiles) { KV_LOAD(buf ^ 1, (t + 1) * 64); cp_commit(); }

        // ---- S = Q K^T (this warp: 16 rows x 64 cols) ----
        float s[8][4];
        #pragma unroll
        for (int nt = 0; nt < 8; nt++)
            #pragma unroll
            for (int j = 0; j < 4; j++) s[nt][j] = 0.0f;

        const unsigned kb = sK + (unsigned)(buf * 9216) + koff;
        #pragma unroll
        for (int ks = 0; ks < 4; ks++) {
            #pragma unroll
            for (int np = 0; np < 4; np++) {
                unsigned k0r, k1r, k2r, k3r;
                ldsm4(k0r, k1r, k2r, k3r, kb + np * 2304 + ks * 32);
                mma16816(s[2 * np],     qa[ks], k0r, k1r);
                mma16816(s[2 * np + 1], qa[ks], k2r, k3r);
            }
        }

        // ---- softmax (registers; compacted bias, contiguous; P via ex2.f16x2) ----
        const int kb0 = t * 64 + cc2;
        float mx0 = NEG_BIG, mx1 = NEG_BIG;
        #pragma unroll
        for (int nt = 0; nt < 8; nt++) {
            float2 b0v = *(const float2*)&lbr0[kb0 + nt * 8];
            float2 b1v = *(const float2*)&lbr1[kb0 + nt * 8];
            s[nt][0] += b0v.x; s[nt][1] += b0v.y;
            s[nt][2] += b1v.x; s[nt][3] += b1v.y;
            mx0 = fmaxf(mx0, fmaxf(s[nt][0], s[nt][1]));
            mx1 = fmaxf(mx1, fmaxf(s[nt][2], s[nt][3]));
        }
        mx0 = fmaxf(mx0, __shfl_xor_sync(0xffffffffu, mx0, 1));
        mx0 = fmaxf(mx0, __shfl_xor_sync(0xffffffffu, mx0, 2));
        mx1 = fmaxf(mx1, __shfl_xor_sync(0xffffffffu, mx1, 1));
        mx1 = fmaxf(mx1, __shfl_xor_sync(0xffffffffu, mx1, 2));

        const float mn0 = fmaxf(m0, mx0), mn1 = fmaxf(m1, mx1);
        const float al0 = __expf(m0 - mn0), al1 = __expf(m1 - mn1);
        m0 = mn0; m1 = mn1;
        #pragma unroll
        for (int nt = 0; nt < 9; nt++) {
            oc[nt][0] *= al0; oc[nt][1] *= al0;
            oc[nt][2] *= al1; oc[nt][3] *= al1;
        }

        unsigned pa[4][4];
        #pragma unroll
        for (int ks = 0; ks < 4; ks++) {
            pa[ks][0] = pack_ex2(s[2 * ks][0],     s[2 * ks][1],     mn0);
            pa[ks][1] = pack_ex2(s[2 * ks][2],     s[2 * ks][3],     mn1);
            pa[ks][2] = pack_ex2(s[2 * ks + 1][0], s[2 * ks + 1][1], mn0);
            pa[ks][3] = pack_ex2(s[2 * ks + 1][2], s[2 * ks + 1][3], mn1);
        }

        // ---- O += P V  (+ ones column -> l in oc[8]) ----
        const unsigned vb = sV + (unsigned)(buf * 9216);
        #pragma unroll
        for (int ks = 0; ks < 4; ks++) {
            #pragma unroll
            for (int np = 0; np < 4; np++) {
                unsigned v0r, v1r, v2r, v3r;
                ldsm4t(v0r, v1r, v2r, v3r, vb + ks * 2304 + np * 32 + voff);
                mma16816(oc[2 * np],     pa[ks], v0r, v1r);
                mma16816(oc[2 * np + 1], pa[ks], v2r, v3r);
            }
            unsigned o0r, o1r;
            ldsm2t(o0r, o1r, vb + ks * 2304 + ooff);
            mma16816(oc[8], pa[ks], o0r, o1r);
        }
    }
    #undef KV_LOAD

    // ---- finalize: l = oc[8] col 64 (lane c==0), broadcast, normalize ----
    const float l0 = __shfl_sync(0xffffffffu, oc[8][0], lane & ~3);
    const float l1 = __shfl_sync(0xffffffffu, oc[8][2], lane & ~3);
    const float inv0 = 1.0f / l0, inv1 = 1.0f / l1;

    __half* d0 = &outh[(size_t)(b * LQ_ + q0 + qw0 + rowid) * 1024 + hc + cc2];
    __half* d1 = d0 + 8 * 1024;
    #pragma unroll
    for (int nt = 0; nt < 8; nt++) {
        *(__half2*)&d0[nt * 8] = __floats2half2_rn(oc[nt][0] * inv0, oc[nt][1] * inv0);
        *(__half2*)&d1[nt * 8] = __floats2half2_rn(oc[nt][2] * inv1, oc[nt][3] * inv1);
    }
}

// ---------------- launch ------------------------------------------------------
extern "C" void kernel_launch(void* const* d_in, const int* in_sizes, int n_in,
                              void* d_out, int out_size)
{
    const float* q    = (const float*)d_in[0];
    const float* k    = (const float*)d_in[1];
    const float* v    = (const float*)d_in[2];
    const float* Wq   = (const float*)d_in[3];
    const float* bq   = (const float*)d_in[4];
    const float* Wk   = (const float*)d_in[5];
    const float* bk   = (const float*)d_in[6];
    const float* Wv   = (const float*)d_in[7];
    const float* bv   = (const float*)d_in[8];
    const float* Wo   = (const float*)d_in[9];
    const float* bo   = (const float*)d_in[10];
    const float* lb   = (const float*)d_in[11];
    const void*  mask = (const void*)d_in[12];
    float* out = (float*)d_out;

    __half *xh3, *wh4, *qh, *kh, *vh;
    cudaGetSymbolAddress((void**)&xh3, g_xh3);
    cudaGetSymbolAddress((void**)&wh4, g_wh4);
    cudaGetSymbolAddress((void**)&qh, g_qh);
    cudaGetSymbolAddress((void**)&kh, g_kh);
    cudaGetSymbolAddress((void**)&vh, g_vh);

    cudaFuncSetAttribute(gemm_qkv,   cudaFuncAttributeMaxDynamicSharedMemorySize, GEMM_SMEM);
    cudaFuncSetAttribute(gemm_out,   cudaFuncAttributeMaxDynamicSharedMemorySize, GEMM_SMEM);
    cudaFuncSetAttribute(flash_attn, cudaFuncAttributeMaxDynamicSharedMemorySize, FLASH_SMEM);

    // compaction maps + mask dtype
    prep_kernel<<<1, 64>>>(mask);

    // zero K/V tail rows; compact bias; stage inputs+weights to half
    fill_tail_kernel<<<dim3(B_, 2), 256>>>();
    cvt_all<<<dim3(1024, 1, 7), 256>>>(q, k, v, Wq, Wk, Wv, Wo, xh3, wh4);
    compact_bias_kernel<<<dim3(LQ_, B_), 256>>>(lb);

    // batched Q/K/V projections; K/V rows scattered into compacted layout
    gemm_qkv<<<dim3(8, 16, 3), 256, GEMM_SMEM>>>(xh3, wh4, bq, bk, bv, qh, kh, vh);

    // fused FA2 attention over compacted keys -> half att into staging slot 0
    flash_attn<<<dim3(LQ_ / 128, BH_), 256, FLASH_SMEM>>>(xh3);

    // output projection
    gemm_out<<<dim3(8, 16), 256, GEMM_SMEM>>>(xh3, wh4 + (size_t)3 * 1024 * 1024, bo, out);
}

// round 17
// speedup vs baseline: 1.4946x; 1.4946x over previous
#include <cuda_runtime.h>
#include <cuda_fp16.h>
#include <mma.h>
#include <math.h>
#include <cstdint>

using namespace nvcuda;

#define B_   2
#define LQ_  1024
#define LK_  1024
#define D_   1024
#define H_   16
#define DH_  64
#define BH_  (B_ * H_)
#define NEG_BIG (-3.402823466e38f)
#define L2E_ 1.44269504f

// ---------------- scratch ----------------------------------------------------
__device__ __half g_xh3[3 * 2048 * 1024];         // staged inputs q/k/v (half); slot0 reused for att
__device__ __half g_wh4[4 * 1024 * 1024];         // staged weights Wq/Wk/Wv/Wo (half)
__device__ __half g_qh[2048 * 1024];              // projected Q (half)
__device__ __half g_kh[2048 * 1024];              // projected K (half)
__device__ __half g_vh[2048 * 1024];              // projected V (half)
__device__ int    g_mask_kind;

// ---------------- helpers -----------------------------------------------------
__device__ __forceinline__ void cp16(unsigned int dst, const void* src) {
    asm volatile("cp.async.cg.shared.global [%0], [%1], 16;\n" :: "r"(dst), "l"(src));
}
__device__ __forceinline__ void cp_commit() {
    asm volatile("cp.async.commit_group;\n" ::: "memory");
}
__device__ __forceinline__ unsigned int smem_u32(const void* ptr) {
    unsigned int a;
    asm("{ .reg .u64 t; cvta.to.shared.u64 t, %1; cvt.u32.u64 %0, t; }" : "=r"(a) : "l"(ptr));
    return a;
}
__device__ __forceinline__ void ldsm4(unsigned& r0, unsigned& r1, unsigned& r2, unsigned& r3,
                                      unsigned addr) {
    asm volatile("ldmatrix.sync.aligned.m8n8.x4.shared.b16 {%0,%1,%2,%3}, [%4];"
                 : "=r"(r0), "=r"(r1), "=r"(r2), "=r"(r3) : "r"(addr));
}
__device__ __forceinline__ void ldsm4t(unsigned& r0, unsigned& r1, unsigned& r2, unsigned& r3,
                                       unsigned addr) {
    asm volatile("ldmatrix.sync.aligned.m8n8.x4.trans.shared.b16 {%0,%1,%2,%3}, [%4];"
                 : "=r"(r0), "=r"(r1), "=r"(r2), "=r"(r3) : "r"(addr));
}
__device__ __forceinline__ void ldsm2t(unsigned& r0, unsigned& r1, unsigned addr) {
    asm volatile("ldmatrix.sync.aligned.m8n8.x2.trans.shared.b16 {%0,%1}, [%2];"
                 : "=r"(r0), "=r"(r1) : "r"(addr));
}
__device__ __forceinline__ void mma16816(float* d, const unsigned* a, unsigned b0, unsigned b1) {
    asm volatile(
        "mma.sync.aligned.m16n8k16.row.col.f32.f16.f16.f32 "
        "{%0,%1,%2,%3}, {%4,%5,%6,%7}, {%8,%9}, {%0,%1,%2,%3};"
        : "+f"(d[0]), "+f"(d[1]), "+f"(d[2]), "+f"(d[3])
        : "r"(a[0]), "r"(a[1]), "r"(a[2]), "r"(a[3]), "r"(b0), "r"(b1));
}
__device__ __forceinline__ unsigned pack_ex2(float x, float y, float mn) {
    __half2 t = __floats2half2_rn((x - mn) * L2E_, (y - mn) * L2E_);
    unsigned u = *reinterpret_cast<unsigned*>(&t);
    unsigned r;
    asm("ex2.approx.f16x2 %0, %1;" : "=r"(r) : "r"(u));
    return r;
}

// ---------------- mask dtype detection --------------------------------------
__global__ void detect_mask_kernel(const unsigned int* m) {
    if (threadIdx.x == 0 && blockIdx.x == 0) {
        int all01 = 1, allf = 1;
        for (int i = 0; i < 512; i++) {
            unsigned v = m[i];
            if (v > 1u) all01 = 0;
            if (v != 0u && v != 0x3F800000u) allf = 0;
        }
        g_mask_kind = all01 ? 0 : (allf ? 1 : 2);
    }
}

__device__ __forceinline__ bool mask_true(const void* m, int kind, int idx) {
    if (kind == 0) return ((const int*)m)[idx] != 0;
    if (kind == 1) return ((const float*)m)[idx] != 0.0f;
    return ((const unsigned char*)m)[idx] != 0;
}

// ---------------- fp32 -> fp16 convert (single launch, 7 slices) -------------
__device__ __forceinline__ void cvt8(const float* __restrict__ x, __half* __restrict__ y, int i) {
    float4 a = *(const float4*)&x[i];
    float4 b = *(const float4*)&x[i + 4];
    __half h[8];
    h[0] = __float2half_rn(a.x); h[1] = __float2half_rn(a.y);
    h[2] = __float2half_rn(a.z); h[3] = __float2half_rn(a.w);
    h[4] = __float2half_rn(b.x); h[5] = __float2half_rn(b.y);
    h[6] = __float2half_rn(b.z); h[7] = __float2half_rn(b.w);
    *(uint4*)&y[i] = *(uint4*)h;
}

__global__ __launch_bounds__(256) void cvt_all(
    const float* __restrict__ q, const float* __restrict__ k, const float* __restrict__ v,
    const float* __restrict__ w0, const float* __restrict__ w1,
    const float* __restrict__ w2, const float* __restrict__ w3,
    __half* __restrict__ xh3, __half* __restrict__ wh4)
{
    const int z = blockIdx.z;
    const int i = (blockIdx.x * 256 + threadIdx.x) * 8;
    if (z < 3) {
        const float* x = (z == 0) ? q : (z == 1) ? k : v;
        cvt8(x, xh3 + (size_t)z * 2048 * 1024, i);
    } else {
        if (i >= 1024 * 1024) return;
        const int wz = z - 3;
        const float* x = (wz == 0) ? w0 : (wz == 1) ? w1 : (wz == 2) ? w2 : w3;
        cvt8(x, wh4 + (size_t)wz * 1024 * 1024, i);
    }
}

// ---------------- fp16 GEMM core: C[2048,1024] = A @ W^T + bias --------------
// BM=128 BN=128 BK=64; 3-stage cp.async pipeline; ONE barrier per K-iter.
#define GEMM_SMEM 110592

__device__ __forceinline__ void gemm_load_stage(
    unsigned int sb, int stage, int m0, int n0, int kc0, int tid,
    const __half* __restrict__ A, const __half* __restrict__ Wm)
{
    const unsigned int base = (unsigned int)(stage * 18432) * 2;
    #pragma unroll
    for (int u = 0; u < 4; u++) {
        int f = tid + u * 256;
        int r = f >> 3, ch = f & 7;
        unsigned int off = base + (unsigned int)(r * 72 + ch * 8) * 2;
        cp16(sb + off,             A  + (size_t)(m0 + r) * 1024 + kc0 + ch * 8);
        cp16(sb + off + 9216 * 2,  Wm + (size_t)(n0 + r) * 1024 + kc0 + ch * 8);
    }
}

__device__ __forceinline__ void gemm_core(
    char* smc, const __half* __restrict__ A, const __half* __restrict__ Wm,
    const float* __restrict__ bias, void* __restrict__ Cout, int out_is_half)
{
    __half* Sh = (__half*)smc;
    float*  Ss = (float*)smc;

    const int tid = threadIdx.x;
    const int w = tid >> 5;
    const int m0 = blockIdx.y * 128, n0 = blockIdx.x * 128;
    const int wm = w >> 2, wn = w & 3;

    const unsigned int sb = smem_u32(Sh);

    wmma::fragment<wmma::accumulator, 16, 16, 16, float> c[4][2];
    #pragma unroll
    for (int i = 0; i < 4; i++)
        #pragma unroll
        for (int j = 0; j < 2; j++)
            wmma::fill_fragment(c[i][j], 0.0f);

    gemm_load_stage(sb, 0, m0, n0, 0,  tid, A, Wm); cp_commit();
    gemm_load_stage(sb, 1, m0, n0, 64, tid, A, Wm); cp_commit();

    for (int t = 0; t < 16; t++) {
        if (t == 15) asm volatile("cp.async.wait_group 0;" ::: "memory");
        else         asm volatile("cp.async.wait_group 1;" ::: "memory");
        __syncthreads();

        if (t + 2 < 16) {
            gemm_load_stage(sb, (t + 2) % 3, m0, n0, (t + 2) * 64, tid, A, Wm);
            cp_commit();
        }

        const __half* Ab = Sh + (t % 3) * 18432;
        const __half* Wb = Ab + 9216;
        #pragma unroll
        for (int kk = 0; kk < 64; kk += 16) {
            wmma::fragment<wmma::matrix_a, 16, 16, 16, __half, wmma::row_major> a[4];
            wmma::fragment<wmma::matrix_b, 16, 16, 16, __half, wmma::col_major> bf[2];
            #pragma unroll
            for (int i = 0; i < 4; i++)
                wmma::load_matrix_sync(a[i], Ab + (wm * 64 + i * 16) * 72 + kk, 72);
            #pragma unroll
            for (int j = 0; j < 2; j++)
                wmma::load_matrix_sync(bf[j], Wb + (wn * 32 + j * 16) * 72 + kk, 72);
            #pragma unroll
            for (int i = 0; i < 4; i++)
                #pragma unroll
                for (int j = 0; j < 2; j++)
                    wmma::mma_sync(c[i][j], a[i], bf[j], c[i][j]);
        }
    }

    __syncthreads();
    #pragma unroll
    for (int i = 0; i < 4; i++)
        #pragma unroll
        for (int j = 0; j < 2; j++)
            wmma::store_matrix_sync(&Ss[(wm * 64 + i * 16) * 132 + wn * 32 + j * 16],
                                    c[i][j], 132, wmma::mem_row_major);
    __syncthreads();

    if (out_is_half) {
        __half* C = (__half*)Cout;
        #pragma unroll
        for (int u = 0; u < 8; u++) {
            int f = tid + u * 256;
            int r = f >> 4, ch = f & 15;
            const float* src = &Ss[r * 132 + ch * 8];
            const float* bp = &bias[n0 + ch * 8];
            __half hv[8];
            #pragma unroll
            for (int e = 0; e < 8; e++) hv[e] = __float2half_rn(src[e] + bp[e]);
            *(uint4*)&C[(size_t)(m0 + r) * 1024 + n0 + ch * 8] = *(uint4*)hv;
        }
    } else {
        float* C = (float*)Cout;
        #pragma unroll
        for (int u = 0; u < 8; u++) {
            int f = tid + u * 256;
            int r = f >> 4, ch = f & 15;
            const float* src = &Ss[r * 132 + ch * 8];
            const float* bp = &bias[n0 + ch * 8];
            float ov[8];
            #pragma unroll
            for (int e = 0; e < 8; e++) ov[e] = src[e] + bp[e];
            *(float4*)&C[(size_t)(m0 + r) * 1024 + n0 + ch * 8] = *(float4*)ov;
            *(float4*)&C[(size_t)(m0 + r) * 1024 + n0 + ch * 8 + 4] = *(float4*)&ov[4];
        }
    }
}

__global__ __launch_bounds__(256) void gemm_qkv(
    const __half* __restrict__ Abase, const __half* __restrict__ Wbase,
    const float* __restrict__ b0, const float* __restrict__ b1, const float* __restrict__ b2,
    __half* __restrict__ C0, __half* __restrict__ C1, __half* __restrict__ C2)
{
    extern __shared__ char smc[];
    const int z = blockIdx.z;
    const float* bias = (z == 0) ? b0 : (z == 1) ? b1 : b2;
    __half* C = (z == 0) ? C0 : (z == 1) ? C1 : C2;
    gemm_core(smc, Abase + (size_t)z * 2048 * 1024,
              Wbase + (size_t)z * 1024 * 1024, bias, C, 1);
}

__global__ __launch_bounds__(256) void gemm_out(
    const __half* __restrict__ A, const __half* __restrict__ Wm,
    const float* __restrict__ bias, float* __restrict__ C)
{
    extern __shared__ char smc[];
    gemm_core(smc, A, Wm, bias, C, 0);
}

// ---------------- flash attention (FA2, 4 warps x 32 q-rows) -----------------
// q-tile 128 (4 warps x 2 row-blocks of 16), k-tile 64; each K/V ldmatrix
// fragment feeds TWO row-block MMAs (halved L1 traffic per MMA).
// smem: msm[1024]f + Qs[128][72]h + Ks[2][64][72]h + Vs[2][64][72]h = 59392 B
#define FLASH_SMEM 59392

__global__ __launch_bounds__(128, 2) void flash_attn(
    const void* __restrict__ mask, const float* __restrict__ lb,
    __half* __restrict__ outh)
{
    extern __shared__ char smc[];
    float*  msm = (float*)smc;                     // [1024] mask additive
    __half* Qs = (__half*)(smc + 4096);            // [128][72]
    __half* Ks = Qs + 128 * 72;                    // [2][64][72]
    __half* Vs = Ks + 2 * 64 * 72;                 // [2][64][72]

    const int tid = threadIdx.x;
    const int w = tid >> 5, lane = tid & 31;
    const int q0 = blockIdx.x * 128;
    const int bh = blockIdx.y;
    const int b = bh >> 4, h = bh & 15;
    const int hc = h * DH_;
    const int kind = g_mask_kind;
    const int qw0 = w * 32;
    const int rowid = lane >> 2, cc2 = (lane & 3) * 2;

    const unsigned sQ = smem_u32(Qs);
    const unsigned sK = smem_u32(Ks);
    const unsigned sV = smem_u32(Vs);

    // mask additive row (shared by all q rows of this batch)
    for (int i = tid; i < 1024; i += 128)
        msm[i] = mask_true(mask, kind, b * LK_ + i) ? NEG_BIG : 0.0f;

    // stage Q (x0.125), 128x64 half
    const __half2 sc2 = __float2half2_rn(0.125f);
    #pragma unroll
    for (int u = 0; u < 8; u++) {
        int f = tid + u * 128;
        int r = f >> 3, ch = f & 7;
        uint4 qv = *(const uint4*)&g_qh[(size_t)(b * LQ_ + q0 + r) * 1024 + hc + ch * 8];
        __half2* qp = (__half2*)&qv;
        #pragma unroll
        for (int e = 0; e < 4; e++) qp[e] = __hmul2(qp[e], sc2);
        *(uint4*)&Qs[r * 72 + ch * 8] = qv;
    }
    // ones column (col 64) + zero pad (65..71) for V, both buffers
    for (int i = tid; i < 128; i += 128) {
        int bu = i >> 6, r = i & 63;
        uint4 z; z.x = 0x00003C00u; z.y = 0u; z.z = 0u; z.w = 0u;
        *(uint4*)&Vs[bu * 64 * 72 + r * 72 + 64] = z;
    }

    #define KV_LOAD(buf, kc0)                                                        \
    {                                                                                \
        _Pragma("unroll")                                                            \
        for (int u = 0; u < 4; u++) {                                                \
            int f = tid + u * 128;                                                   \
            int r = f >> 3, ch = f & 7;                                              \
            unsigned int off = (unsigned)((buf) * 64 * 72 + r * 72 + ch * 8) * 2;    \
            size_t g = (size_t)(b * LK_ + (kc0) + r) * 1024 + hc + ch * 8;           \
            cp16(sK + off, &g_kh[g]);                                                \
            cp16(sV + off, &g_vh[g]);                                                \
        }                                                                            \
    }

    KV_LOAD(0, 0); cp_commit();
    __syncthreads();   // Qs (and msm) complete before ldmatrix

    // Q fragments (persistent): qa[rb][ks][0..3]
    unsigned qa[2][4][4];
    #pragma unroll
    for (int rb = 0; rb < 2; rb++) {
        unsigned qaddr = sQ + (unsigned)((qw0 + rb * 16 + ((lane >> 3) & 1) * 8 + (lane & 7)) * 144
                                         + (lane >> 4) * 16);
        #pragma unroll
        for (int ks = 0; ks < 4; ks++)
            ldsm4(qa[rb][ks][0], qa[rb][ks][1], qa[rb][ks][2], qa[rb][ks][3], qaddr + ks * 32);
    }

    // ldmatrix lane-offsets
    const unsigned koff = (unsigned)(((lane >> 4) * 8 + (lane & 7)) * 144 + ((lane >> 3) & 1) * 16);
    const unsigned voff = (unsigned)(((( lane >> 3) & 1) * 8 + (lane & 7)) * 144 + (lane >> 4) * 16);
    const unsigned ooff = (unsigned)(((( lane >> 3) & 1) * 8 + (lane & 7)) * 144 + 128);

    float oc[2][9][4];
    #pragma unroll
    for (int rb = 0; rb < 2; rb++)
        #pragma unroll
        for (int nt = 0; nt < 9; nt++)
            #pragma unroll
            for (int j = 0; j < 4; j++) oc[rb][nt][j] = 0.0f;
    float mm[2][2];
    mm[0][0] = NEG_BIG; mm[0][1] = NEG_BIG; mm[1][0] = NEG_BIG; mm[1][1] = NEG_BIG;

    const float* lbbase = lb + (size_t)(b * LQ_ + q0 + qw0 + rowid) * 1024;

    for (int t = 0; t < 16; t++) {
        const int buf = t & 1;
        asm volatile("cp.async.wait_group 0;" ::: "memory");
        __syncthreads();
        if (t + 1 < 16) { KV_LOAD(buf ^ 1, (t + 1) * 64); cp_commit(); }

        // ---- S = Q K^T (this warp: 32 rows x 64 cols; K frags reused x2) ----
        float s[2][8][4];
        #pragma unroll
        for (int rb = 0; rb < 2; rb++)
            #pragma unroll
            for (int nt = 0; nt < 8; nt++)
                #pragma unroll
                for (int j = 0; j < 4; j++) s[rb][nt][j] = 0.0f;

        const unsigned kb = sK + (unsigned)(buf * 9216) + koff;
        #pragma unroll
        for (int ks = 0; ks < 4; ks++) {
            #pragma unroll
            for (int np = 0; np < 4; np++) {
                unsigned k0r, k1r, k2r, k3r;
                ldsm4(k0r, k1r, k2r, k3r, kb + np * 2304 + ks * 32);
                #pragma unroll
                for (int rb = 0; rb < 2; rb++) {
                    mma16816(s[rb][2 * np],     qa[rb][ks], k0r, k1r);
                    mma16816(s[rb][2 * np + 1], qa[rb][ks], k2r, k3r);
                }
            }
        }

        // ---- softmax per row-block (registers; P via ex2.f16x2) ----
        const int kb0 = t * 64 + cc2;
        unsigned pa[2][4][4];
        #pragma unroll
        for (int rb = 0; rb < 2; rb++) {
            const float* lbr0 = lbbase + rb * 16 * 1024;
            const float* lbr1 = lbr0 + 8 * 1024;
            float mx0 = NEG_BIG, mx1 = NEG_BIG;
            #pragma unroll
            for (int nt = 0; nt < 8; nt++) {
                float2 md = *(float2*)&msm[kb0 + nt * 8];
                float2 b0v = *(const float2*)&lbr0[kb0 + nt * 8];
                float2 b1v = *(const float2*)&lbr1[kb0 + nt * 8];
                s[rb][nt][0] += b0v.x + md.x; s[rb][nt][1] += b0v.y + md.y;
                s[rb][nt][2] += b1v.x + md.x; s[rb][nt][3] += b1v.y + md.y;
                mx0 = fmaxf(mx0, fmaxf(s[rb][nt][0], s[rb][nt][1]));
                mx1 = fmaxf(mx1, fmaxf(s[rb][nt][2], s[rb][nt][3]));
            }
            mx0 = fmaxf(mx0, __shfl_xor_sync(0xffffffffu, mx0, 1));
            mx0 = fmaxf(mx0, __shfl_xor_sync(0xffffffffu, mx0, 2));
            mx1 = fmaxf(mx1, __shfl_xor_sync(0xffffffffu, mx1, 1));
            mx1 = fmaxf(mx1, __shfl_xor_sync(0xffffffffu, mx1, 2));

            const float mn0 = fmaxf(mm[rb][0], mx0), mn1 = fmaxf(mm[rb][1], mx1);
            const float al0 = __expf(mm[rb][0] - mn0), al1 = __expf(mm[rb][1] - mn1);
            mm[rb][0] = mn0; mm[rb][1] = mn1;
            #pragma unroll
            for (int nt = 0; nt < 9; nt++) {
                oc[rb][nt][0] *= al0; oc[rb][nt][1] *= al0;
                oc[rb][nt][2] *= al1; oc[rb][nt][3] *= al1;
            }
            #pragma unroll
            for (int ks = 0; ks < 4; ks++) {
                pa[rb][ks][0] = pack_ex2(s[rb][2 * ks][0],     s[rb][2 * ks][1],     mn0);
                pa[rb][ks][1] = pack_ex2(s[rb][2 * ks][2],     s[rb][2 * ks][3],     mn1);
                pa[rb][ks][2] = pack_ex2(s[rb][2 * ks + 1][0], s[rb][2 * ks + 1][1], mn0);
                pa[rb][ks][3] = pack_ex2(s[rb][2 * ks + 1][2], s[rb][2 * ks + 1][3], mn1);
            }
        }

        // ---- O += P V  (+ ones column -> l in oc[rb][8]; V frags reused x2) ----
        const unsigned vb = sV + (unsigned)(buf * 9216);
        #pragma unroll
        for (int ks = 0; ks < 4; ks++) {
            #pragma unroll
            for (int np = 0; np < 4; np++) {
                unsigned v0r, v1r, v2r, v3r;
                ldsm4t(v0r, v1r, v2r, v3r, vb + ks * 2304 + np * 32 + voff);
                #pragma unroll
                for (int rb = 0; rb < 2; rb++) {
                    mma16816(oc[rb][2 * np],     pa[rb][ks], v0r, v1r);
                    mma16816(oc[rb][2 * np + 1], pa[rb][ks], v2r, v3r);
                }
            }
            unsigned o0r, o1r;
            ldsm2t(o0r, o1r, vb + ks * 2304 + ooff);
            #pragma unroll
            for (int rb = 0; rb < 2; rb++)
                mma16816(oc[rb][8], pa[rb][ks], o0r, o1r);
        }
    }
    #undef KV_LOAD

    // ---- finalize per row-block: l from ones-column, broadcast, normalize ----
    #pragma unroll
    for (int rb = 0; rb < 2; rb++) {
        const float l0 = __shfl_sync(0xffffffffu, oc[rb][8][0], lane & ~3);
        const float l1 = __shfl_sync(0xffffffffu, oc[rb][8][2], lane & ~3);
        const float inv0 = 1.0f / l0, inv1 = 1.0f / l1;

        __half* d0 = &outh[(size_t)(b * LQ_ + q0 + qw0 + rb * 16 + rowid) * 1024 + hc + cc2];
        __half* d1 = d0 + 8 * 1024;
        #pragma unroll
        for (int nt = 0; nt < 8; nt++) {
            *(__half2*)&d0[nt * 8] = __floats2half2_rn(oc[rb][nt][0] * inv0, oc[rb][nt][1] * inv0);
            *(__half2*)&d1[nt * 8] = __floats2half2_rn(oc[rb][nt][2] * inv1, oc[rb][nt][3] * inv1);
        }
    }
}

// ---------------- launch ------------------------------------------------------
extern "C" void kernel_launch(void* const* d_in, const int* in_sizes, int n_in,
                              void* d_out, int out_size)
{
    const float* q    = (const float*)d_in[0];
    const float* k    = (const float*)d_in[1];
    const float* v    = (const float*)d_in[2];
    const float* Wq   = (const float*)d_in[3];
    const float* bq   = (const float*)d_in[4];
    const float* Wk   = (const float*)d_in[5];
    const float* bk   = (const float*)d_in[6];
    const float* Wv   = (const float*)d_in[7];
    const float* bv   = (const float*)d_in[8];
    const float* Wo   = (const float*)d_in[9];
    const float* bo   = (const float*)d_in[10];
    const float* lb   = (const float*)d_in[11];
    const void*  mask = (const void*)d_in[12];
    float* out = (float*)d_out;

    __half *xh3, *wh4, *qh, *kh, *vh;
    cudaGetSymbolAddress((void**)&xh3, g_xh3);
    cudaGetSymbolAddress((void**)&wh4, g_wh4);
    cudaGetSymbolAddress((void**)&qh, g_qh);
    cudaGetSymbolAddress((void**)&kh, g_kh);
    cudaGetSymbolAddress((void**)&vh, g_vh);

    cudaFuncSetAttribute(gemm_qkv,   cudaFuncAttributeMaxDynamicSharedMemorySize, GEMM_SMEM);
    cudaFuncSetAttribute(gemm_out,   cudaFuncAttributeMaxDynamicSharedMemorySize, GEMM_SMEM);
    cudaFuncSetAttribute(flash_attn, cudaFuncAttributeMaxDynamicSharedMemorySize, FLASH_SMEM);

    detect_mask_kernel<<<1, 32>>>(( const unsigned int*)mask);

    // stage all inputs + weights to half (ONE launch)
    cvt_all<<<dim3(1024, 1, 7), 256>>>(q, k, v, Wq, Wk, Wv, Wo, xh3, wh4);

    // batched Q/K/V projections (one launch, 384 CTAs)
    gemm_qkv<<<dim3(8, 16, 3), 256, GEMM_SMEM>>>(xh3, wh4, bq, bk, bv, qh, kh, vh);

    // fused FA2 attention -> half att directly into staging slot 0
    flash_attn<<<dim3(LQ_ / 128, BH_), 128, FLASH_SMEM>>>(mask, lb, xh3);

    // output projection
    gemm_out<<<dim3(8, 16), 256, GEMM_SMEM>>>(xh3, wh4 + (size_t)3 * 1024 * 1024, bo, out);
}